// round 1
// baseline (speedup 1.0000x reference)
#include <cuda_runtime.h>
#include <cstdint>

#define BATCH 64
#define DIM   524288
#define PROJ  8192
#define CVAL  4

#define NCHUNK  32          // D-chunks
#define BTILE   4           // batch rows per CTA
#define BGROUPS (BATCH / BTILE)   // 16
#define CHUNK   (DIM / NCHUNK)    // 16384
#define THREADS 1024

// Scratch (allocation-free rule: __device__ globals)
__device__ unsigned long long g_packed[DIM];                       // 4 MB
__device__ float g_partials[(size_t)BATCH * NCHUNK * PROJ];        // 64 MB

// ---------------------------------------------------------------------------
// Kernel 1: pack (idx, sign) pairs: 4 x uint16 (p<<1 | s) per d into uint64.
// ---------------------------------------------------------------------------
__global__ void pack_kernel(const int* __restrict__ idx, const int* __restrict__ sgn) {
    int d = blockIdx.x * blockDim.x + threadIdx.x;
    if (d >= DIM) return;
    int4 iv = ((const int4*)idx)[d];
    int4 sv = ((const int4*)sgn)[d];
    unsigned long long p0 = (unsigned)((iv.x << 1) | sv.x) & 0xFFFFu;
    unsigned long long p1 = (unsigned)((iv.y << 1) | sv.y) & 0xFFFFu;
    unsigned long long p2 = (unsigned)((iv.z << 1) | sv.z) & 0xFFFFu;
    unsigned long long p3 = (unsigned)((iv.w << 1) | sv.w) & 0xFFFFu;
    g_packed[d] = p0 | (p1 << 16) | (p2 << 32) | (p3 << 48);
}

// ---------------------------------------------------------------------------
// Kernel 2: scatter into SMEM accumulators (BTILE batch rows per CTA),
// commit partials (no gmem atomics).
// grid = (NCHUNK, BGROUPS), 1024 threads, 128 KB dynamic smem.
// ---------------------------------------------------------------------------
__global__ void __launch_bounds__(THREADS, 1)
scatter_kernel(const float* __restrict__ x) {
    extern __shared__ float acc[];   // [BTILE][PROJ]  (k-major)

    const int chunk = blockIdx.x;
    const int bg    = blockIdx.y;

    for (int i = threadIdx.x; i < BTILE * PROJ; i += THREADS) acc[i] = 0.0f;
    __syncthreads();

    const int d0 = chunk * CHUNK;
    const float* xb = x + (size_t)bg * BTILE * DIM;

    for (int i = threadIdx.x; i < CHUNK; i += THREADS) {
        const int d = d0 + i;
        const unsigned long long pk = g_packed[d];
        const unsigned x0 = __float_as_uint(xb[d]);
        const unsigned x1 = __float_as_uint(xb[(size_t)DIM + d]);
        const unsigned x2 = __float_as_uint(xb[2 * (size_t)DIM + d]);
        const unsigned x3 = __float_as_uint(xb[3 * (size_t)DIM + d]);
        #pragma unroll
        for (int j = 0; j < CVAL; j++) {
            const unsigned e  = (unsigned)(pk >> (16 * j)) & 0xFFFFu;
            const unsigned p  = e >> 1;
            const unsigned sm = ((e & 1u) ^ 1u) << 31;   // sign bit 0 -> negate
            atomicAdd(&acc[p],            __uint_as_float(x0 ^ sm));
            atomicAdd(&acc[PROJ + p],     __uint_as_float(x1 ^ sm));
            atomicAdd(&acc[2 * PROJ + p], __uint_as_float(x2 ^ sm));
            atomicAdd(&acc[3 * PROJ + p], __uint_as_float(x3 ^ sm));
        }
    }
    __syncthreads();

    // Commit: partials layout [b][chunk][p] -> coalesced reads in reduce.
    for (int i = threadIdx.x; i < BTILE * PROJ; i += THREADS) {
        const int k = i >> 13;        // /PROJ
        const int p = i & (PROJ - 1);
        const int b = bg * BTILE + k;
        g_partials[((size_t)b * NCHUNK + chunk) * PROJ + p] = acc[i];
    }
}

// ---------------------------------------------------------------------------
// Kernel 3: reduce partials over chunks, apply 1/sqrt(C) = 0.5.
// ---------------------------------------------------------------------------
__global__ void reduce_kernel(float* __restrict__ out) {
    const int idx = blockIdx.x * blockDim.x + threadIdx.x;   // over BATCH*PROJ
    if (idx >= BATCH * PROJ) return;
    const int b = idx >> 13;
    const int p = idx & (PROJ - 1);
    const float* base = g_partials + (size_t)b * NCHUNK * PROJ + p;
    float s = 0.0f;
    #pragma unroll
    for (int c = 0; c < NCHUNK; c++) s += base[(size_t)c * PROJ];
    out[idx] = 0.5f * s;
}

extern "C" void kernel_launch(void* const* d_in, const int* in_sizes, int n_in,
                              void* d_out, int out_size) {
    const float* x   = (const float*)d_in[0];
    const int*   idx = (const int*)d_in[1];
    const int*   sgn = (const int*)d_in[2];
    float*       out = (float*)d_out;

    cudaFuncSetAttribute(scatter_kernel,
                         cudaFuncAttributeMaxDynamicSharedMemorySize,
                         BTILE * PROJ * sizeof(float));

    pack_kernel<<<(DIM + 255) / 256, 256>>>(idx, sgn);

    dim3 grid(NCHUNK, BGROUPS);
    scatter_kernel<<<grid, THREADS, BTILE * PROJ * sizeof(float)>>>(x);

    reduce_kernel<<<(BATCH * PROJ + 255) / 256, 256>>>(out);
}

// round 3
// speedup vs baseline: 1.0458x; 1.0458x over previous
#include <cuda_runtime.h>
#include <cstdint>

#define BATCH 64
#define DIM   524288
#define PROJ  8192
#define CVAL  4

#define NCHUNK  32          // D-chunks
#define BTILE   4           // batch rows per CTA
#define BGROUPS (BATCH / BTILE)   // 16
#define CHUNK   (DIM / NCHUNK)    // 16384
#define THREADS 1024

// Scratch (allocation-free rule: __device__ globals)
__device__ unsigned long long g_packed[DIM];                       // 4 MB
__device__ float g_partials[(size_t)BATCH * NCHUNK * PROJ];        // 64 MB

// ---------------------------------------------------------------------------
// Kernel 1: pack (idx, sign) pairs: 4 x uint16 (p<<1 | s) per d into uint64.
// ---------------------------------------------------------------------------
__global__ void pack_kernel(const int* __restrict__ idx, const int* __restrict__ sgn) {
    int d = blockIdx.x * blockDim.x + threadIdx.x;
    if (d >= DIM) return;
    int4 iv = ((const int4*)idx)[d];
    int4 sv = ((const int4*)sgn)[d];
    unsigned long long p0 = (unsigned)((iv.x << 1) | sv.x) & 0xFFFFu;
    unsigned long long p1 = (unsigned)((iv.y << 1) | sv.y) & 0xFFFFu;
    unsigned long long p2 = (unsigned)((iv.z << 1) | sv.z) & 0xFFFFu;
    unsigned long long p3 = (unsigned)((iv.w << 1) | sv.w) & 0xFFFFu;
    g_packed[d] = p0 | (p1 << 16) | (p2 << 32) | (p3 << 48);
}

// ---------------------------------------------------------------------------
// Kernel 2: scatter into SMEM accumulators (BTILE batch rows per CTA),
// commit partials (no gmem atomics).
// grid = (NCHUNK, BGROUPS), 1024 threads, 128 KB dynamic smem.
// ---------------------------------------------------------------------------
__global__ void __launch_bounds__(THREADS, 1)
scatter_kernel(const float* __restrict__ x) {
    extern __shared__ float acc[];   // [BTILE][PROJ]  (k-major)

    const int chunk = blockIdx.x;
    const int bg    = blockIdx.y;

    for (int i = threadIdx.x; i < BTILE * PROJ; i += THREADS) acc[i] = 0.0f;
    __syncthreads();

    const int d0 = chunk * CHUNK;
    const float* xb = x + (size_t)bg * BTILE * DIM;

    for (int i = threadIdx.x; i < CHUNK; i += THREADS) {
        const int d = d0 + i;
        const unsigned long long pk = g_packed[d];
        const unsigned x0 = __float_as_uint(xb[d]);
        const unsigned x1 = __float_as_uint(xb[(size_t)DIM + d]);
        const unsigned x2 = __float_as_uint(xb[2 * (size_t)DIM + d]);
        const unsigned x3 = __float_as_uint(xb[3 * (size_t)DIM + d]);
        #pragma unroll
        for (int j = 0; j < CVAL; j++) {
            const unsigned e  = (unsigned)(pk >> (16 * j)) & 0xFFFFu;
            const unsigned p  = e >> 1;
            const unsigned sm = ((e & 1u) ^ 1u) << 31;   // sign bit 0 -> negate
            atomicAdd(&acc[p],            __uint_as_float(x0 ^ sm));
            atomicAdd(&acc[PROJ + p],     __uint_as_float(x1 ^ sm));
            atomicAdd(&acc[2 * PROJ + p], __uint_as_float(x2 ^ sm));
            atomicAdd(&acc[3 * PROJ + p], __uint_as_float(x3 ^ sm));
        }
    }
    __syncthreads();

    // Commit: partials layout [b][chunk][p] -> coalesced reads in reduce.
    for (int i = threadIdx.x; i < BTILE * PROJ; i += THREADS) {
        const int k = i >> 13;        // /PROJ
        const int p = i & (PROJ - 1);
        const int b = bg * BTILE + k;
        g_partials[((size_t)b * NCHUNK + chunk) * PROJ + p] = acc[i];
    }
}

// ---------------------------------------------------------------------------
// Kernel 3: reduce partials over chunks, apply 1/sqrt(C) = 0.5.
// ---------------------------------------------------------------------------
__global__ void reduce_kernel(float* __restrict__ out) {
    const int idx = blockIdx.x * blockDim.x + threadIdx.x;   // over BATCH*PROJ
    if (idx >= BATCH * PROJ) return;
    const int b = idx >> 13;
    const int p = idx & (PROJ - 1);
    const float* base = g_partials + (size_t)b * NCHUNK * PROJ + p;
    float s = 0.0f;
    #pragma unroll
    for (int c = 0; c < NCHUNK; c++) s += base[(size_t)c * PROJ];
    out[idx] = 0.5f * s;
}

extern "C" void kernel_launch(void* const* d_in, const int* in_sizes, int n_in,
                              void* d_out, int out_size) {
    const float* x   = (const float*)d_in[0];
    const int*   idx = (const int*)d_in[1];
    const int*   sgn = (const int*)d_in[2];
    float*       out = (float*)d_out;

    cudaFuncSetAttribute(scatter_kernel,
                         cudaFuncAttributeMaxDynamicSharedMemorySize,
                         BTILE * PROJ * sizeof(float));

    pack_kernel<<<(DIM + 255) / 256, 256>>>(idx, sgn);

    dim3 grid(NCHUNK, BGROUPS);
    scatter_kernel<<<grid, THREADS, BTILE * PROJ * sizeof(float)>>>(x);

    reduce_kernel<<<(BATCH * PROJ + 255) / 256, 256>>>(out);
}

// round 4
// speedup vs baseline: 2.1405x; 2.0468x over previous
#include <cuda_runtime.h>
#include <cuda_fp16.h>
#include <cstdint>

#define BATCH 64
#define DIM   524288
#define PROJ  8192
#define CVAL  4
#define BCAP  512          // per-bucket capacity (mean 256, Poisson tail @512 ~ 1e-46)

// ----------------------------- device scratch ------------------------------
__device__ __align__(16) unsigned short g_xh[(size_t)DIM * BATCH]; // fp16 xT[d][b], 64 MB
__device__ unsigned g_entries[(size_t)PROJ * BCAP];                // 16 MB
__device__ int g_cursor[PROJ];

// ---------------------------------------------------------------------------
// Kernel 1: transpose x[64][DIM] fp32 -> g_xh[DIM][64] fp16. Also zero cursors.
// grid 8192 x 256 threads; CTA handles 64 d-columns.
// ---------------------------------------------------------------------------
__global__ void __launch_bounds__(256)
transpose_kernel(const float* __restrict__ x) {
    __shared__ float tile[64][65];

    if (blockIdx.x < 8) {   // zero the 8192 cursors (8 CTAs x 256 x int4)
        reinterpret_cast<int4*>(g_cursor)[blockIdx.x * 256 + threadIdx.x] =
            make_int4(0, 0, 0, 0);
    }

    const int d0 = blockIdx.x * 64;
    const int t  = threadIdx.x;

    // Phase 1: coalesced read. Half-warp reads one row chunk (16 x float4 = 64 floats).
    {
        const int col = (t & 15) * 4;
        const int b0  = t >> 4;            // 0..15
        #pragma unroll
        for (int r = 0; r < 4; r++) {
            const int b = r * 16 + b0;
            float4 v = *reinterpret_cast<const float4*>(x + (size_t)b * DIM + d0 + col);
            tile[col + 0][b] = v.x;
            tile[col + 1][b] = v.y;
            tile[col + 2][b] = v.z;
            tile[col + 3][b] = v.w;
        }
    }
    __syncthreads();

    // Phase 2: convert + coalesced write. Thread t: row dd = t>>2, quarter = t&3.
    {
        const int dd   = t >> 2;
        const int part = t & 3;
        __half2 h[8];
        #pragma unroll
        for (int j = 0; j < 8; j++) {
            h[j] = __floats2half2_rn(tile[dd][part * 16 + 2 * j],
                                     tile[dd][part * 16 + 2 * j + 1]);
        }
        uint4* dst = reinterpret_cast<uint4*>(g_xh + (size_t)(d0 + dd) * 64 + part * 16);
        dst[0] = *reinterpret_cast<uint4*>(&h[0]);
        dst[1] = *reinterpret_cast<uint4*>(&h[4]);
    }
}

// ---------------------------------------------------------------------------
// Kernel 2: bucket placement. One thread per d: 4 instances -> buckets.
// record = (d << 1) | sign
// ---------------------------------------------------------------------------
__global__ void __launch_bounds__(256)
place_kernel(const int* __restrict__ idx, const int* __restrict__ sgn) {
    const int d = blockIdx.x * 256 + threadIdx.x;
    const int4 iv = reinterpret_cast<const int4*>(idx)[d];
    const int4 sv = reinterpret_cast<const int4*>(sgn)[d];
    const unsigned rec = (unsigned)d << 1;
    int p, pos;
    p = iv.x; pos = atomicAdd(&g_cursor[p], 1); g_entries[(size_t)p * BCAP + pos] = rec | sv.x;
    p = iv.y; pos = atomicAdd(&g_cursor[p], 1); g_entries[(size_t)p * BCAP + pos] = rec | sv.y;
    p = iv.z; pos = atomicAdd(&g_cursor[p], 1); g_entries[(size_t)p * BCAP + pos] = rec | sv.z;
    p = iv.w; pos = atomicAdd(&g_cursor[p], 1); g_entries[(size_t)p * BCAP + pos] = rec | sv.w;
}

// ---------------------------------------------------------------------------
// Kernel 3: gather. One warp per bucket p. 8 lanes/group cover the 64-batch
// row (8 fp16 each); 4 groups walk the entry list in parallel. Register
// accumulation, shfl reduction, coalesced store via smem.
// grid 1024 x 256 (8 warps/CTA).
// ---------------------------------------------------------------------------
__global__ void __launch_bounds__(256)
gather_kernel(float* __restrict__ out) {
    __shared__ float s_res[64][8];

    const int warp = threadIdx.x >> 5;
    const int lane = threadIdx.x & 31;
    const int p    = blockIdx.x * 8 + warp;
    const int g    = lane >> 3;      // entry group 0..3
    const int sub  = lane & 7;       // batch octet 0..7

    const int count = g_cursor[p];
    const unsigned* ent = g_entries + (size_t)p * BCAP;

    float acc[8] = {0.f, 0.f, 0.f, 0.f, 0.f, 0.f, 0.f, 0.f};

    for (int i = g; i < count; i += 4) {
        const unsigned rec = ent[i];
        const uint4 raw = *reinterpret_cast<const uint4*>(
            g_xh + ((size_t)(rec >> 1) << 6) + (sub << 3));
        const float s = (rec & 1u) ? 1.0f : -1.0f;
        const float2 f0 = __half22float2(*reinterpret_cast<const __half2*>(&raw.x));
        const float2 f1 = __half22float2(*reinterpret_cast<const __half2*>(&raw.y));
        const float2 f2 = __half22float2(*reinterpret_cast<const __half2*>(&raw.z));
        const float2 f3 = __half22float2(*reinterpret_cast<const __half2*>(&raw.w));
        acc[0] = fmaf(s, f0.x, acc[0]);
        acc[1] = fmaf(s, f0.y, acc[1]);
        acc[2] = fmaf(s, f1.x, acc[2]);
        acc[3] = fmaf(s, f1.y, acc[3]);
        acc[4] = fmaf(s, f2.x, acc[4]);
        acc[5] = fmaf(s, f2.y, acc[5]);
        acc[6] = fmaf(s, f3.x, acc[6]);
        acc[7] = fmaf(s, f3.y, acc[7]);
    }

    // Reduce the 4 entry-groups (lanes l, l^8, l^16, l^24 share `sub`).
    #pragma unroll
    for (int k = 0; k < 8; k++) {
        acc[k] += __shfl_xor_sync(0xFFFFFFFFu, acc[k], 8);
        acc[k] += __shfl_xor_sync(0xFFFFFFFFu, acc[k], 16);
    }

    if (lane < 8) {
        #pragma unroll
        for (int k = 0; k < 8; k++)
            s_res[sub * 8 + k][warp] = 0.5f * acc[k];   // scale 1/sqrt(4)
    }
    __syncthreads();

    // Coalesced-ish store: thread t writes float2 of out[b][p0 + part*2].
    {
        const int b    = threadIdx.x >> 2;
        const int part = threadIdx.x & 3;
        float2 v = make_float2(s_res[b][part * 2], s_res[b][part * 2 + 1]);
        *reinterpret_cast<float2*>(out + (size_t)b * PROJ + blockIdx.x * 8 + part * 2) = v;
    }
}

extern "C" void kernel_launch(void* const* d_in, const int* in_sizes, int n_in,
                              void* d_out, int out_size) {
    const float* x   = (const float*)d_in[0];
    const int*   idx = (const int*)d_in[1];
    const int*   sgn = (const int*)d_in[2];
    float*       out = (float*)d_out;

    transpose_kernel<<<DIM / 64, 256>>>(x);
    place_kernel<<<DIM / 256, 256>>>(idx, sgn);
    gather_kernel<<<PROJ / 8, 256>>>(out);
}